// round 4
// baseline (speedup 1.0000x reference)
#include <cuda_runtime.h>
#include <math.h>

#define TPB 256

// shared layout (floats)
#define LDH   128            // h row stride
#define LDS1  388            // s1 row stride (qkv / scratch), 388%32=4, mult of 4 for float4
#define LDKT  69             // kT row stride (k-transposed), 69%32=5 -> conflict-free
#define LDSTG 132            // weight stage row stride (128+4), float4 conflict-free

#define OFF_H   0
#define OFF_S1  8704                     // h: 68*128
#define OFF_KT  (OFF_S1 + 68*LDS1)      // s1: 68*388 = 26384
#define OFF_STG (OFF_KT + 128*LDKT)     // kT: 128*69 = 8832
#define SMEM_FLOATS (OFF_STG + 8448)    // stage: 64*132 = 8448
// total = 8704+26384+8832+8448 = 52368 floats = 209472 bytes

__device__ __forceinline__ float4 ld4(const float* p) {
    return *reinterpret_cast<const float4*>(p);
}
__device__ __forceinline__ float warp_sum(float v) {
#pragma unroll
    for (int o = 16; o > 0; o >>= 1) v += __shfl_xor_sync(0xffffffffu, v, o);
    return v;
}
__device__ __forceinline__ float warp_max(float v) {
#pragma unroll
    for (int o = 16; o > 0; o >>= 1) v = fmaxf(v, __shfl_xor_sync(0xffffffffu, v, o));
    return v;
}

// GEMM: out[t][j] = A[t][:] . Wg[j][:] + bias[j], t in [0,65), j in [0,J)
// A in smem (rows padded to 68), Wg global row-major [J][K], K in {128,256}, J mult of 64.
// Stage: 64 W-rows x 128 k-chunk in smem. Warp w owns t-tiles tt = w, w+8, w+16.
// TRANSPOSED=1 stores Out[j*LDKT + t] (for k^T); RELU applies max(0,.).
template<int TRANSPOSED, int RELU>
__device__ void gemm_sm(const float* __restrict__ A, int lda,
                        const float* __restrict__ Wg, int K, int J,
                        const float* __restrict__ bias,
                        float* __restrict__ Out, int ldo,
                        float* __restrict__ stg,
                        int tid, int lane, int wid)
{
    const int nkb = K >> 7;
    const int njb = J >> 6;
    for (int jb = 0; jb < njb; ++jb) {
        float acc[3][4][2];
#pragma unroll
        for (int s = 0; s < 3; ++s)
#pragma unroll
            for (int i = 0; i < 4; ++i) { acc[s][i][0] = 0.f; acc[s][i][1] = 0.f; }

        for (int kb = 0; kb < nkb; ++kb) {
            __syncthreads();                       // protect stage from previous users
            const float* wsrc = Wg + (jb * 64) * K + kb * 128;
#pragma unroll
            for (int i = tid; i < 2048; i += TPB) {        // 64 rows x 32 float4
                int j  = i >> 5;
                int k4 = (i & 31) << 2;
                *reinterpret_cast<float4*>(stg + j * LDSTG + k4) = ld4(wsrc + j * K + k4);
            }
            __syncthreads();
#pragma unroll
            for (int s = 0; s < 3; ++s) {
                int tt = wid + s * 8;
                if (tt < 17) {
                    const float* Ab  = A + tt * 4 * lda + kb * 128;
                    const float* wp0 = stg + lane * LDSTG;
                    const float* wp1 = wp0 + 32 * LDSTG;
#pragma unroll 4
                    for (int k4 = 0; k4 < 128; k4 += 4) {
                        float4 w0 = ld4(wp0 + k4);
                        float4 w1 = ld4(wp1 + k4);
#pragma unroll
                        for (int i = 0; i < 4; ++i) {
                            float4 a = ld4(Ab + i * lda + k4);
                            acc[s][i][0] = fmaf(a.x, w0.x, acc[s][i][0]);
                            acc[s][i][0] = fmaf(a.y, w0.y, acc[s][i][0]);
                            acc[s][i][0] = fmaf(a.z, w0.z, acc[s][i][0]);
                            acc[s][i][0] = fmaf(a.w, w0.w, acc[s][i][0]);
                            acc[s][i][1] = fmaf(a.x, w1.x, acc[s][i][1]);
                            acc[s][i][1] = fmaf(a.y, w1.y, acc[s][i][1]);
                            acc[s][i][1] = fmaf(a.z, w1.z, acc[s][i][1]);
                            acc[s][i][1] = fmaf(a.w, w1.w, acc[s][i][1]);
                        }
                    }
                }
            }
        }
        // store
#pragma unroll
        for (int s = 0; s < 3; ++s) {
            int tt = wid + s * 8;
            if (tt >= 17) continue;
#pragma unroll
            for (int r = 0; r < 2; ++r) {
                int j = jb * 64 + lane + 32 * r;
                float bv = bias[j];
#pragma unroll
                for (int i = 0; i < 4; ++i) {
                    int t = tt * 4 + i;
                    if (t < 65) {
                        float v = acc[s][i][r] + bv;
                        if (RELU) v = fmaxf(v, 0.f);
                        if (TRANSPOSED) Out[j * LDKT + t] = v;
                        else            Out[t * ldo + j]  = v;
                    }
                }
            }
        }
    }
}

// h[t] = LN(h[t] + g[t]) * sc + bt  for t < 65; g has row stride LDS1
__device__ __forceinline__ void layer_norm_res(float* __restrict__ h,
                                               const float* __restrict__ g,
                                               const float* __restrict__ sc,
                                               const float* __restrict__ bt,
                                               int lane, int wid)
{
    for (int t = wid; t < 65; t += 8) {
        float v[4];
        float s = 0.f;
#pragma unroll
        for (int i = 0; i < 4; ++i) {
            int c = lane + 32 * i;
            v[i] = h[t * LDH + c] + g[t * LDS1 + c];
            s += v[i];
        }
        s = warp_sum(s);
        float mean = s * 0.0078125f;
        float var = 0.f;
#pragma unroll
        for (int i = 0; i < 4; ++i) { float d = v[i] - mean; var = fmaf(d, d, var); }
        var = warp_sum(var) * 0.0078125f;
        float r = rsqrtf(var + 1e-5f);
#pragma unroll
        for (int i = 0; i < 4; ++i) {
            int c = lane + 32 * i;
            h[t * LDH + c] = (v[i] - mean) * r * sc[c] + bt[c];
        }
    }
}

__global__ void __launch_bounds__(TPB, 1)
vit_kernel(const float* __restrict__ x,
           const float* __restrict__ patch_w,
           const float* __restrict__ patch_b,
           const float* __restrict__ cls_token,
           const float* __restrict__ pos_embed,
           const float* __restrict__ qkv_w,
           const float* __restrict__ qkv_b,
           const float* __restrict__ out_w,
           const float* __restrict__ out_b,
           const float* __restrict__ ln1_s,
           const float* __restrict__ ln1_b,
           const float* __restrict__ ln2_s,
           const float* __restrict__ ln2_b,
           const float* __restrict__ ff1_w,
           const float* __restrict__ ff1_b,
           const float* __restrict__ ff2_w,
           const float* __restrict__ ff2_b,
           const float* __restrict__ qr1_w,
           const float* __restrict__ qr1_b,
           const float* __restrict__ qr2_w,
           const float* __restrict__ qr2_b,
           const float* __restrict__ q_weights,
           const float* __restrict__ clf_w,
           const float* __restrict__ clf_b,
           float* __restrict__ y)
{
    extern __shared__ float sm[];
    float* h   = sm + OFF_H;    // [68][128]
    float* s1  = sm + OFF_S1;   // [68][388]: q 0..127 | k-out/attn-scratch 128..255 | v 256..383
    float* kT  = sm + OFF_KT;   // [128][69]
    float* stg = sm + OFF_STG;  // 8448 floats: W stage / x image / softmax probs

    const int tid  = threadIdx.x;
    const int lane = tid & 31;
    const int wid  = tid >> 5;
    const int b    = blockIdx.x;

    // ---------------- patch embed ----------------
    const float* xb = x + (size_t)b * 3072;
    for (int i = tid; i < 3072; i += TPB) stg[i] = xb[i];
    for (int i = tid; i < 6144; i += TPB) {          // patch_w [d][ck] -> s1[ck][d]
        int d = i / 48, ck = i - d * 48;
        s1[ck * 128 + d] = patch_w[i];
    }
    __syncthreads();
    for (int idx = tid; idx < 8192; idx += TPB) {
        int tkn = idx >> 7, d = idx & 127;
        int pi = tkn >> 3, pj = tkn & 7;
        const float* xp = stg + pi * 128 + pj * 4;
        float acc = patch_b[d];
#pragma unroll
        for (int c = 0; c < 3; ++c)
#pragma unroll
            for (int p = 0; p < 4; ++p)
#pragma unroll
                for (int q = 0; q < 4; ++q)
                    acc = fmaf(xp[c * 1024 + p * 32 + q], s1[(c * 16 + p * 4 + q) * 128 + d], acc);
        h[(1 + tkn) * LDH + d] = acc + pos_embed[(1 + tkn) * 128 + d];
    }
    for (int d = tid; d < 128; d += TPB) h[d] = cls_token[d] + pos_embed[d];
    // gemm's leading __syncthreads orders these writes before stage reuse.

    const float SCALE = 0.17677669529663687f;   // 1/sqrt(32)

    for (int li = 0; li < 4; ++li) {
        const float* qw = qkv_w + li * 49152;
        const float* qb = qkv_b + li * 384;
        // Q -> s1[:,0:128]
        gemm_sm<0, 0>(h, LDH, qw,          128, 128, qb,        s1,        LDS1, stg, tid, lane, wid);
        // K -> kT (transposed)
        gemm_sm<1, 0>(h, LDH, qw + 16384,  128, 128, qb + 128,  kT,        0,    stg, tid, lane, wid);
        // V -> s1[:,256:384]
        gemm_sm<0, 0>(h, LDH, qw + 32768,  128, 128, qb + 256,  s1 + 256,  LDS1, stg, tid, lane, wid);
        __syncthreads();   // kT / v visible to all warps

        // ---------------- attention (row partition == warp id, no block syncs) ----------------
        for (int hd = 0; hd < 4; ++hd) {
            const int ho = hd * 32;
            for (int tt = wid; tt < 17; tt += 8) {
                const int t0 = tt * 4;
                float a0[4], a1[4], a64[4];
#pragma unroll
                for (int i = 0; i < 4; ++i) { a0[i] = 0.f; a1[i] = 0.f; a64[i] = 0.f; }
                const float* qrow = s1 + t0 * LDS1 + ho;
                const float* kb   = kT + ho * LDKT;
#pragma unroll 8
                for (int k = 0; k < 32; ++k) {
                    float k0  = kb[k * LDKT + lane];
                    float k1  = kb[k * LDKT + 32 + lane];
                    float k64 = kb[k * LDKT + 64];
#pragma unroll
                    for (int i = 0; i < 4; ++i) {
                        float qv = qrow[i * LDS1 + k];
                        a0[i]  = fmaf(qv, k0,  a0[i]);
                        a1[i]  = fmaf(qv, k1,  a1[i]);
                        a64[i] = fmaf(qv, k64, a64[i]);
                    }
                }
                // softmax rows t0..t0+3 (guarded), probs -> stg[t][u], stride 68
#pragma unroll
                for (int i = 0; i < 4; ++i) {
                    int t = t0 + i;
                    if (t >= 65) break;
                    float v0 = a0[i] * SCALE, v1 = a1[i] * SCALE, v2 = a64[i] * SCALE;
                    float m = warp_max(fmaxf(fmaxf(v0, v1), v2));
                    float e0 = expf(v0 - m), e1 = expf(v1 - m), e2 = expf(v2 - m);
                    float ssum = warp_sum(e0 + e1 + (lane == 0 ? e2 : 0.f));
                    float inv = 1.f / ssum;
                    stg[t * 68 + lane]      = e0 * inv;
                    stg[t * 68 + 32 + lane] = e1 * inv;
                    if (lane == 0) stg[t * 68 + 64] = e2 * inv;
                }
                __syncwarp();
                // O = S @ V_h, write into q-slot of this head (already consumed)
                float oc[4] = {0.f, 0.f, 0.f, 0.f};
                const float* vb = s1 + 256 + ho + lane;
                for (int u = 0; u < 65; ++u) {
                    float vv = vb[u * LDS1];
#pragma unroll
                    for (int i = 0; i < 4; ++i)
                        oc[i] = fmaf(stg[(t0 + i) * 68 + u], vv, oc[i]);
                }
#pragma unroll
                for (int i = 0; i < 4; ++i)
                    if (t0 + i < 65) s1[(t0 + i) * LDS1 + ho + lane] = oc[i];
                __syncwarp();
            }
        }

        // out-proj: s1[:,0:128] @ W^T -> s1[:,128:256]
        gemm_sm<0, 0>(s1, LDS1, out_w + li * 16384, 128, 128, out_b + li * 128,
                      s1 + 128, LDS1, stg, tid, lane, wid);
        __syncthreads();
        layer_norm_res(h, s1 + 128, ln1_s + li * 128, ln1_b + li * 128, lane, wid);
        __syncthreads();

        // FF1 (relu) -> s1[:,0:256]
        gemm_sm<0, 1>(h, LDH, ff1_w + li * 32768, 128, 256, ff1_b + li * 256,
                      s1, LDS1, stg, tid, lane, wid);
        // FF2 -> s1[:,256:384]   (reads s1[:,0:256], K=256)
        gemm_sm<0, 0>(s1, LDS1, ff2_w + li * 32768, 256, 128, ff2_b + li * 128,
                      s1 + 256, LDS1, stg, tid, lane, wid);
        __syncthreads();
        layer_norm_res(h, s1 + 256, ln2_s + li * 128, ln2_b + li * 128, lane, wid);
        __syncthreads();
    }

    // ---------------- readout head (warp 0) ----------------
    if (wid == 0) {
        // a = relu(cls @ qr1_w^T + qr1_b), lane j = feature j
        float accq = qr1_b[lane];
        const float* wr = qr1_w + lane * 128;
#pragma unroll 8
        for (int k = 0; k < 128; k += 4) {
            float4 hv = ld4(h + k);
            float4 wv = ld4(wr + k);
            accq = fmaf(hv.x, wv.x, accq);
            accq = fmaf(hv.y, wv.y, accq);
            accq = fmaf(hv.z, wv.z, accq);
            accq = fmaf(hv.w, wv.w, accq);
        }
        stg[lane] = fmaxf(accq, 0.f);
        __syncwarp();
        float qo[4];
#pragma unroll
        for (int m = 0; m < 4; ++m) {
            float s = qr2_b[m];
            for (int k = 0; k < 32; ++k) s = fmaf(stg[k], qr2_w[m * 32 + k], s);
            float qin = tanhf(s);
            qo[m] = cosf(qin) * cosf(q_weights[m]);
        }
        qo[1] *= qo[0]; qo[2] *= qo[1]; qo[3] *= qo[2];   // cumprod
        if (lane < 10) {
            float o = clf_b[lane];
            const float* cw = clf_w + lane * 132;
            for (int k = 0; k < 128; ++k) o = fmaf(h[k], cw[k], o);
#pragma unroll
            for (int m = 0; m < 4; ++m) o = fmaf(qo[m], cw[128 + m], o);
            y[b * 10 + lane] = o;
        }
    }
}

extern "C" void kernel_launch(void* const* d_in, const int* in_sizes, int n_in,
                              void* d_out, int out_size)
{
    const int B = in_sizes[0] / 3072;   // x = (B,3,32,32)
    cudaFuncSetAttribute(vit_kernel, cudaFuncAttributeMaxDynamicSharedMemorySize,
                         SMEM_FLOATS * (int)sizeof(float));
    vit_kernel<<<B, TPB, SMEM_FLOATS * sizeof(float)>>>(
        (const float*)d_in[0],  (const float*)d_in[1],  (const float*)d_in[2],
        (const float*)d_in[3],  (const float*)d_in[4],  (const float*)d_in[5],
        (const float*)d_in[6],  (const float*)d_in[7],  (const float*)d_in[8],
        (const float*)d_in[9],  (const float*)d_in[10], (const float*)d_in[11],
        (const float*)d_in[12], (const float*)d_in[13], (const float*)d_in[14],
        (const float*)d_in[15], (const float*)d_in[16], (const float*)d_in[17],
        (const float*)d_in[18], (const float*)d_in[19], (const float*)d_in[20],
        (const float*)d_in[21], (const float*)d_in[22], (const float*)d_in[23],
        (float*)d_out);
}

// round 5
// speedup vs baseline: 1.0504x; 1.0504x over previous
#include <cuda_runtime.h>
#include <math.h>

#define TPB 512
#define NW  16
typedef unsigned long long u64;

// shared layout (floats)
#define LDH   128            // h row stride
#define LDS_  264            // S row stride: q 0..127 | v/ff1b 132..259
#define LDKT  69             // kT row stride (conflict-free)
#define LDW   134            // weight stage row stride: lane*134 %32 = 6*lane -> conflict-free LDS.64

#define OFF_H   0
#define OFF_S   8704                      // h: 68*128
#define OFF_KT  (OFF_S + 68*LDS_)         // S: 68*264 = 17952 -> 26656   (kT / G share this area)
#define OFF_STG (OFF_KT + 128*LDKT)       // kT: 8832 -> 35488
#define SMEM_FLOATS (OFF_STG + 128*LDW)   // stage: 17152 -> 52640 floats = 210560 B

__device__ __forceinline__ float4 ld4(const float* p) {
    return *reinterpret_cast<const float4*>(p);
}
__device__ __forceinline__ u64 pack2(float x, float y) {
    u64 r; asm("mov.b64 %0, {%1, %2};" : "=l"(r) : "f"(x), "f"(y)); return r;
}
__device__ __forceinline__ void ffma2(u64& d, u64 a, u64 b) {
    asm("fma.rn.f32x2 %0, %1, %2, %0;" : "+l"(d) : "l"(a), "l"(b));
}
__device__ __forceinline__ float2 unpk(u64 v) {
    float2 r; asm("mov.b64 {%0, %1}, %2;" : "=f"(r.x), "=f"(r.y) : "l"(v)); return r;
}
__device__ __forceinline__ float warp_sum(float v) {
#pragma unroll
    for (int o = 16; o > 0; o >>= 1) v += __shfl_xor_sync(0xffffffffu, v, o);
    return v;
}
__device__ __forceinline__ float warp_max(float v) {
#pragma unroll
    for (int o = 16; o > 0; o >>= 1) v = fmaxf(v, __shfl_xor_sync(0xffffffffu, v, o));
    return v;
}

// GEMM: Out[t][j] = A[t][:] . Wg[j][:] + bias[j], t in [0,65), J = 128 per call.
// K = nkb*128; A k-chunk kb starts at A + kb*kstride. W row-major, row stride wld.
// Warp tile: 8 rows x 64 cols (rt = wid>>1 rows rt*8..+7, jh = wid&1 cols jh*64 + {lane, lane+32}).
// Row 64 handled by an all-warp gemv (warp w owns j = 8w..8w+7).
// Packed f32x2 FMA over k-pairs; acc halves summed at store time.
template<int TRANSPOSED, int RELU>
__device__ void gemm128(const float* __restrict__ A, int lda, int kstride, int nkb,
                        const float* __restrict__ Wg, int wld,
                        const float* __restrict__ bias,
                        float* __restrict__ Out, int ldo,
                        float* __restrict__ stg,
                        int tid, int lane, int wid)
{
    const int rt = wid >> 1;
    const int jb = ((wid & 1) << 6) + lane;    // cols jb, jb+32
    u64 acc[8][2];
#pragma unroll
    for (int i = 0; i < 8; ++i) { acc[i][0] = 0ull; acc[i][1] = 0ull; }
    float accg[8] = {0.f, 0.f, 0.f, 0.f, 0.f, 0.f, 0.f, 0.f};

    for (int kb = 0; kb < nkb; ++kb) {
        __syncthreads();                       // protect stage from previous users
        const float* wb = Wg + kb * 128;
        for (int idx = tid; idx < 4096; idx += TPB) {   // 128 j-rows x 32 float4
            int j  = idx & 127;
            int k4 = (idx >> 7) << 2;
            float4 v = ld4(wb + j * wld + k4);
            float* d = stg + j * LDW + k4;
            *reinterpret_cast<float2*>(d)     = make_float2(v.x, v.y);
            *reinterpret_cast<float2*>(d + 2) = make_float2(v.z, v.w);
        }
        __syncthreads();

        const float* Ab  = A + kb * kstride + rt * 8 * lda;
        const float* w0p = stg + jb * LDW;
        const float* w1p = w0p + 32 * LDW;
#pragma unroll 4
        for (int k4 = 0; k4 < 128; k4 += 4) {
            u64 w00 = *reinterpret_cast<const u64*>(w0p + k4);
            u64 w01 = *reinterpret_cast<const u64*>(w0p + k4 + 2);
            u64 w10 = *reinterpret_cast<const u64*>(w1p + k4);
            u64 w11 = *reinterpret_cast<const u64*>(w1p + k4 + 2);
#pragma unroll
            for (int i = 0; i < 8; ++i) {
                float4 a = ld4(Ab + i * lda + k4);
                u64 a01 = pack2(a.x, a.y);
                u64 a23 = pack2(a.z, a.w);
                ffma2(acc[i][0], a01, w00);
                ffma2(acc[i][0], a23, w01);
                ffma2(acc[i][1], a01, w10);
                ffma2(acc[i][1], a23, w11);
            }
        }
        // row 64 gemv partials (all warps; lane-split over k)
        const float* A64 = A + 64 * lda + kb * kstride;
        float av0 = A64[lane], av1 = A64[lane + 32], av2 = A64[lane + 64], av3 = A64[lane + 96];
#pragma unroll
        for (int jj = 0; jj < 8; ++jj) {
            const float* wc = stg + ((wid << 3) + jj) * LDW;
            accg[jj] = fmaf(av0, wc[lane],      accg[jj]);
            accg[jj] = fmaf(av1, wc[lane + 32], accg[jj]);
            accg[jj] = fmaf(av2, wc[lane + 64], accg[jj]);
            accg[jj] = fmaf(av3, wc[lane + 96], accg[jj]);
        }
    }

    float b0 = bias[jb], b1 = bias[jb + 32];
#pragma unroll
    for (int i = 0; i < 8; ++i) {
        int t = rt * 8 + i;
        float2 f0 = unpk(acc[i][0]);
        float2 f1 = unpk(acc[i][1]);
        float v0 = f0.x + f0.y + b0;
        float v1 = f1.x + f1.y + b1;
        if (RELU) { v0 = fmaxf(v0, 0.f); v1 = fmaxf(v1, 0.f); }
        if (TRANSPOSED) {
            Out[jb * LDKT + t]        = v0;
            Out[(jb + 32) * LDKT + t] = v1;
        } else {
            Out[t * ldo + jb]      = v0;
            Out[t * ldo + jb + 32] = v1;
        }
    }
#pragma unroll
    for (int jj = 0; jj < 8; ++jj) {
        float s = warp_sum(accg[jj]);
        if (lane == jj) {
            int j = (wid << 3) + jj;
            float v = s + bias[j];
            if (RELU) v = fmaxf(v, 0.f);
            if (TRANSPOSED) Out[j * LDKT + 64] = v;
            else            Out[64 * ldo + j]  = v;
        }
    }
}

// h[t] = LN(h[t] + g[t]) * sc + bt  for t < 65; g has row stride ldg
__device__ __forceinline__ void layer_norm_res(float* __restrict__ h,
                                               const float* __restrict__ g, int ldg,
                                               const float* __restrict__ sc,
                                               const float* __restrict__ bt,
                                               int lane, int wid)
{
    for (int t = wid; t < 65; t += NW) {
        float v[4];
        float s = 0.f;
#pragma unroll
        for (int i = 0; i < 4; ++i) {
            int c = lane + 32 * i;
            v[i] = h[t * LDH + c] + g[t * ldg + c];
            s += v[i];
        }
        s = warp_sum(s);
        float mean = s * 0.0078125f;
        float var = 0.f;
#pragma unroll
        for (int i = 0; i < 4; ++i) { float d = v[i] - mean; var = fmaf(d, d, var); }
        var = warp_sum(var) * 0.0078125f;
        float r = rsqrtf(var + 1e-5f);
#pragma unroll
        for (int i = 0; i < 4; ++i) {
            int c = lane + 32 * i;
            h[t * LDH + c] = (v[i] - mean) * r * sc[c] + bt[c];
        }
    }
}

__global__ void __launch_bounds__(TPB, 1)
vit_kernel(const float* __restrict__ x,
           const float* __restrict__ patch_w,
           const float* __restrict__ patch_b,
           const float* __restrict__ cls_token,
           const float* __restrict__ pos_embed,
           const float* __restrict__ qkv_w,
           const float* __restrict__ qkv_b,
           const float* __restrict__ out_w,
           const float* __restrict__ out_b,
           const float* __restrict__ ln1_s,
           const float* __restrict__ ln1_b,
           const float* __restrict__ ln2_s,
           const float* __restrict__ ln2_b,
           const float* __restrict__ ff1_w,
           const float* __restrict__ ff1_b,
           const float* __restrict__ ff2_w,
           const float* __restrict__ ff2_b,
           const float* __restrict__ qr1_w,
           const float* __restrict__ qr1_b,
           const float* __restrict__ qr2_w,
           const float* __restrict__ qr2_b,
           const float* __restrict__ q_weights,
           const float* __restrict__ clf_w,
           const float* __restrict__ clf_b,
           float* __restrict__ y)
{
    extern __shared__ float sm[];
    float* h   = sm + OFF_H;    // [68][128]
    float* S   = sm + OFF_S;    // [68][264]: q/ff1a 0..127 | v/ff1b 132..259
    float* kT  = sm + OFF_KT;   // [128][69]; also G = [65][132] out-proj / FF2 output
    float* G   = sm + OFF_KT;
    float* stg = sm + OFF_STG;  // weight stage [128][134] / x image / softmax probs

    const int tid  = threadIdx.x;
    const int lane = tid & 31;
    const int wid  = tid >> 5;
    const int b    = blockIdx.x;

    // ---------------- patch embed ----------------
    const float* xb = x + (size_t)b * 3072;
    for (int i = tid; i < 3072; i += TPB) stg[i] = xb[i];
    for (int i = tid; i < 6144; i += TPB) {          // patch_w [d][ck] -> S[ck][d]
        int d = i / 48, ck = i - d * 48;
        S[ck * 128 + d] = patch_w[i];
    }
    __syncthreads();
    for (int idx = tid; idx < 8192; idx += TPB) {
        int tkn = idx >> 7, d = idx & 127;
        int pi = tkn >> 3, pj = tkn & 7;
        const float* xp = stg + pi * 128 + pj * 4;
        float acc = patch_b[d];
#pragma unroll
        for (int c = 0; c < 3; ++c)
#pragma unroll
            for (int p = 0; p < 4; ++p)
#pragma unroll
                for (int q = 0; q < 4; ++q)
                    acc = fmaf(xp[c * 1024 + p * 32 + q], S[(c * 16 + p * 4 + q) * 128 + d], acc);
        h[(1 + tkn) * LDH + d] = acc + pos_embed[(1 + tkn) * 128 + d];
    }
    for (int d = tid; d < 128; d += TPB) h[d] = cls_token[d] + pos_embed[d];
    // gemm's leading __syncthreads orders these writes before stage reuse.

    const float SCALE = 0.17677669529663687f;   // 1/sqrt(32)

    for (int li = 0; li < 4; ++li) {
        const float* qw = qkv_w + li * 49152;
        const float* qb = qkv_b + li * 384;
        // Q -> S[:,0:128]
        gemm128<0, 0>(h, LDH, 0, 1, qw,          128, qb,        S,       LDS_, stg, tid, lane, wid);
        // K -> kT (transposed)
        gemm128<1, 0>(h, LDH, 0, 1, qw + 16384,  128, qb + 128,  kT,      0,    stg, tid, lane, wid);
        // V -> S[:,132:260]
        gemm128<0, 0>(h, LDH, 0, 1, qw + 32768,  128, qb + 256,  S + 132, LDS_, stg, tid, lane, wid);
        __syncthreads();   // kT / v visible to all warps

        // ---------------- attention: flat unit = (tile, head), warp-private probs ----------------
        {
            float* pw = stg + wid * 272;   // 4 rows x 68 probs
            for (int u = wid; u < 68; u += NW) {
                int hd = u & 3, tt = u >> 2;
                int ho = hd << 5;
                int t0 = tt << 2;
                float a0[4], a1[4], a64[4];
#pragma unroll
                for (int i = 0; i < 4; ++i) { a0[i] = 0.f; a1[i] = 0.f; a64[i] = 0.f; }
                const float* qrow = S + t0 * LDS_ + ho;
                const float* kb   = kT + ho * LDKT;
#pragma unroll 8
                for (int k = 0; k < 32; ++k) {
                    float k0  = kb[k * LDKT + lane];
                    float k1  = kb[k * LDKT + 32 + lane];
                    float k64 = kb[k * LDKT + 64];
#pragma unroll
                    for (int i = 0; i < 4; ++i) {
                        float qv = qrow[i * LDS_ + k];
                        a0[i]  = fmaf(qv, k0,  a0[i]);
                        a1[i]  = fmaf(qv, k1,  a1[i]);
                        a64[i] = fmaf(qv, k64, a64[i]);
                    }
                }
#pragma unroll
                for (int i = 0; i < 4; ++i) {
                    int t = t0 + i;
                    if (t >= 65) break;
                    float v0 = a0[i] * SCALE, v1 = a1[i] * SCALE, v2 = a64[i] * SCALE;
                    float m = warp_max(fmaxf(fmaxf(v0, v1), v2));
                    float e0 = __expf(v0 - m), e1 = __expf(v1 - m), e2 = __expf(v2 - m);
                    float ssum = warp_sum(e0 + e1 + (lane == 0 ? e2 : 0.f));
                    float inv = 1.f / ssum;
                    pw[i * 68 + lane]      = e0 * inv;
                    pw[i * 68 + 32 + lane] = e1 * inv;
                    if (lane == 0) pw[i * 68 + 64] = e2 * inv;
                }
                __syncwarp();
                float oc[4] = {0.f, 0.f, 0.f, 0.f};
                const float* vb = S + 132 + ho + lane;
#pragma unroll 4
                for (int uu = 0; uu < 65; ++uu) {
                    float vv = vb[uu * LDS_];
#pragma unroll
                    for (int i = 0; i < 4; ++i)
                        oc[i] = fmaf(pw[i * 68 + uu], vv, oc[i]);
                }
#pragma unroll
                for (int i = 0; i < 4; ++i)
                    if (t0 + i < 65) S[(t0 + i) * LDS_ + ho + lane] = oc[i];
                __syncwarp();
            }
        }

        // out-proj: S[:,0:128] @ W^T -> G
        gemm128<0, 0>(S, LDS_, 0, 1, out_w + li * 16384, 128, out_b + li * 128,
                      G, 132, stg, tid, lane, wid);
        __syncthreads();
        layer_norm_res(h, G, 132, ln1_s + li * 128, ln1_b + li * 128, lane, wid);

        // FF1 (relu) halves -> S[:,0:128], S[:,132:260]
        gemm128<0, 1>(h, LDH, 0, 1, ff1_w + li * 32768,         128, ff1_b + li * 256,
                      S, LDS_, stg, tid, lane, wid);
        gemm128<0, 1>(h, LDH, 0, 1, ff1_w + li * 32768 + 16384, 128, ff1_b + li * 256 + 128,
                      S + 132, LDS_, stg, tid, lane, wid);
        // FF2 (K=256, two k-stages over the S halves) -> G
        gemm128<0, 0>(S, LDS_, 132, 2, ff2_w + li * 32768, 256, ff2_b + li * 128,
                      G, 132, stg, tid, lane, wid);
        __syncthreads();
        layer_norm_res(h, G, 132, ln2_s + li * 128, ln2_b + li * 128, lane, wid);
    }
    __syncthreads();

    // ---------------- readout head (warp 0) ----------------
    if (wid == 0) {
        float accq = qr1_b[lane];
        const float* wr = qr1_w + lane * 128;
#pragma unroll 8
        for (int k = 0; k < 128; k += 4) {
            float4 hv = ld4(h + k);
            float4 wv = ld4(wr + k);
            accq = fmaf(hv.x, wv.x, accq);
            accq = fmaf(hv.y, wv.y, accq);
            accq = fmaf(hv.z, wv.z, accq);
            accq = fmaf(hv.w, wv.w, accq);
        }
        stg[lane] = fmaxf(accq, 0.f);
        __syncwarp();
        float qo[4];
#pragma unroll
        for (int m = 0; m < 4; ++m) {
            float s = qr2_b[m];
            for (int k = 0; k < 32; ++k) s = fmaf(stg[k], qr2_w[m * 32 + k], s);
            float qin = tanhf(s);
            qo[m] = cosf(qin) * cosf(q_weights[m]);
        }
        qo[1] *= qo[0]; qo[2] *= qo[1]; qo[3] *= qo[2];   // cumprod
        if (lane < 10) {
            float o = clf_b[lane];
            const float* cw = clf_w + lane * 132;
            for (int k = 0; k < 128; ++k) o = fmaf(h[k], cw[k], o);
#pragma unroll
            for (int m = 0; m < 4; ++m) o = fmaf(qo[m], cw[128 + m], o);
            y[b * 10 + lane] = o;
        }
    }
}

extern "C" void kernel_launch(void* const* d_in, const int* in_sizes, int n_in,
                              void* d_out, int out_size)
{
    const int B = in_sizes[0] / 3072;   // x = (B,3,32,32)
    cudaFuncSetAttribute(vit_kernel, cudaFuncAttributeMaxDynamicSharedMemorySize,
                         SMEM_FLOATS * (int)sizeof(float));
    vit_kernel<<<B, TPB, SMEM_FLOATS * sizeof(float)>>>(
        (const float*)d_in[0],  (const float*)d_in[1],  (const float*)d_in[2],
        (const float*)d_in[3],  (const float*)d_in[4],  (const float*)d_in[5],
        (const float*)d_in[6],  (const float*)d_in[7],  (const float*)d_in[8],
        (const float*)d_in[9],  (const float*)d_in[10], (const float*)d_in[11],
        (const float*)d_in[12], (const float*)d_in[13], (const float*)d_in[14],
        (const float*)d_in[15], (const float*)d_in[16], (const float*)d_in[17],
        (const float*)d_in[18], (const float*)d_in[19], (const float*)d_in[20],
        (const float*)d_in[21], (const float*)d_in[22], (const float*)d_in[23],
        (float*)d_out);
}

// round 6
// speedup vs baseline: 1.1037x; 1.0507x over previous
#include <cuda_runtime.h>
#include <math.h>

#define TPB 512
#define NW  16
typedef unsigned long long u64;

// shared layout (floats)
#define LDH   128            // h row stride
#define LDS_  264            // S row stride: q 0..127 | v/ff1b 132..259
#define LDKT  69             // kT row stride (conflict-free)
#define LDW   134            // weight stage row stride: lane*134 %32 = 6*lane -> conflict-free LDS.64

#define OFF_H   0
#define OFF_S   8704                      // h: 68*128
#define OFF_KT  (OFF_S + 68*LDS_)         // S: 68*264 = 17952 -> 26656   (kT / G share this area)
#define OFF_STG (OFF_KT + 128*LDKT)       // kT: 8832 -> 35488
#define SMEM_FLOATS (OFF_STG + 128*LDW)   // stage: 17152 -> 52640 floats = 210560 B

__device__ __forceinline__ float4 ld4(const float* p) {
    return *reinterpret_cast<const float4*>(p);
}
__device__ __forceinline__ u64 pack2(float x, float y) {
    u64 r; asm("mov.b64 %0, {%1, %2};" : "=l"(r) : "f"(x), "f"(y)); return r;
}
__device__ __forceinline__ void ffma2(u64& d, u64 a, u64 b) {
    asm("fma.rn.f32x2 %0, %1, %2, %0;" : "+l"(d) : "l"(a), "l"(b));
}
__device__ __forceinline__ float2 unpk(u64 v) {
    float2 r; asm("mov.b64 {%0, %1}, %2;" : "=f"(r.x), "=f"(r.y) : "l"(v)); return r;
}
__device__ __forceinline__ float warp_sum(float v) {
#pragma unroll
    for (int o = 16; o > 0; o >>= 1) v += __shfl_xor_sync(0xffffffffu, v, o);
    return v;
}
__device__ __forceinline__ float warp_max(float v) {
#pragma unroll
    for (int o = 16; o > 0; o >>= 1) v = fmaxf(v, __shfl_xor_sync(0xffffffffu, v, o));
    return v;
}

// GEMM: Out[t][j] = A[t][:] . Wg[j][:] + bias[j], t in [0,65), J = 128 per call.
// K = nkb*128; A k-chunk kb starts at A + kb*kstride. W row-major, row stride wld.
// Warp tile: 8 rows x 64 cols (rt = wid>>1 rows rt*8..+7, jh = wid&1 cols jh*64 + {lane, lane+32}).
// Row 64 handled by an all-warp gemv (warp w owns j = 8w..8w+7).
// Packed f32x2 FMA over k-pairs; acc halves summed at store time.
template<int TRANSPOSED, int RELU>
__device__ void gemm128(const float* __restrict__ A, int lda, int kstride, int nkb,
                        const float* __restrict__ Wg, int wld,
                        const float* __restrict__ bias,
                        float* __restrict__ Out, int ldo,
                        float* __restrict__ stg,
                        int tid, int lane, int wid)
{
    const int rt = wid >> 1;
    const int jb = ((wid & 1) << 6) + lane;    // cols jb, jb+32
    u64 acc[8][2];
#pragma unroll
    for (int i = 0; i < 8; ++i) { acc[i][0] = 0ull; acc[i][1] = 0ull; }
    float accg[8] = {0.f, 0.f, 0.f, 0.f, 0.f, 0.f, 0.f, 0.f};

    for (int kb = 0; kb < nkb; ++kb) {
        __syncthreads();                       // protect stage from previous users
        const float* wb = Wg + kb * 128;
        for (int idx = tid; idx < 4096; idx += TPB) {   // 128 j-rows x 32 float4
            int j  = idx & 127;
            int k4 = (idx >> 7) << 2;
            float4 v = ld4(wb + j * wld + k4);
            float* d = stg + j * LDW + k4;
            *reinterpret_cast<float2*>(d)     = make_float2(v.x, v.y);
            *reinterpret_cast<float2*>(d + 2) = make_float2(v.z, v.w);
        }
        __syncthreads();

        const float* Ab  = A + kb * kstride + rt * 8 * lda;
        const float* w0p = stg + jb * LDW;
        const float* w1p = w0p + 32 * LDW;
#pragma unroll 4
        for (int k4 = 0; k4 < 128; k4 += 4) {
            u64 w00 = *reinterpret_cast<const u64*>(w0p + k4);
            u64 w01 = *reinterpret_cast<const u64*>(w0p + k4 + 2);
            u64 w10 = *reinterpret_cast<const u64*>(w1p + k4);
            u64 w11 = *reinterpret_cast<const u64*>(w1p + k4 + 2);
#pragma unroll
            for (int i = 0; i < 8; ++i) {
                float4 a = ld4(Ab + i * lda + k4);
                u64 a01 = pack2(a.x, a.y);
                u64 a23 = pack2(a.z, a.w);
                ffma2(acc[i][0], a01, w00);
                ffma2(acc[i][0], a23, w01);
                ffma2(acc[i][1], a01, w10);
                ffma2(acc[i][1], a23, w11);
            }
        }
        // row 64 gemv partials (all warps; lane-split over k)
        const float* A64 = A + 64 * lda + kb * kstride;
        float av0 = A64[lane], av1 = A64[lane + 32], av2 = A64[lane + 64], av3 = A64[lane + 96];
#pragma unroll
        for (int jj = 0; jj < 8; ++jj) {
            const float* wc = stg + ((wid << 3) + jj) * LDW;
            accg[jj] = fmaf(av0, wc[lane],      accg[jj]);
            accg[jj] = fmaf(av1, wc[lane + 32], accg[jj]);
            accg[jj] = fmaf(av2, wc[lane + 64], accg[jj]);
            accg[jj] = fmaf(av3, wc[lane + 96], accg[jj]);
        }
    }

    float b0 = bias[jb], b1 = bias[jb + 32];
#pragma unroll
    for (int i = 0; i < 8; ++i) {
        int t = rt * 8 + i;
        float2 f0 = unpk(acc[i][0]);
        float2 f1 = unpk(acc[i][1]);
        float v0 = f0.x + f0.y + b0;
        float v1 = f1.x + f1.y + b1;
        if (RELU) { v0 = fmaxf(v0, 0.f); v1 = fmaxf(v1, 0.f); }
        if (TRANSPOSED) {
            Out[jb * LDKT + t]        = v0;
            Out[(jb + 32) * LDKT + t] = v1;
        } else {
            Out[t * ldo + jb]      = v0;
            Out[t * ldo + jb + 32] = v1;
        }
    }
#pragma unroll
    for (int jj = 0; jj < 8; ++jj) {
        float s = warp_sum(accg[jj]);
        if (lane == jj) {
            int j = (wid << 3) + jj;
            float v = s + bias[j];
            if (RELU) v = fmaxf(v, 0.f);
            if (TRANSPOSED) Out[j * LDKT + 64] = v;
            else            Out[64 * ldo + j]  = v;
        }
    }
}

// h[t] = LN(h[t] + g[t]) * sc + bt  for t < 65; g has row stride ldg
__device__ __forceinline__ void layer_norm_res(float* __restrict__ h,
                                               const float* __restrict__ g, int ldg,
                                               const float* __restrict__ sc,
                                               const float* __restrict__ bt,
                                               int lane, int wid)
{
    for (int t = wid; t < 65; t += NW) {
        float v[4];
        float s = 0.f;
#pragma unroll
        for (int i = 0; i < 4; ++i) {
            int c = lane + 32 * i;
            v[i] = h[t * LDH + c] + g[t * ldg + c];
            s += v[i];
        }
        s = warp_sum(s);
        float mean = s * 0.0078125f;
        float var = 0.f;
#pragma unroll
        for (int i = 0; i < 4; ++i) { float d = v[i] - mean; var = fmaf(d, d, var); }
        var = warp_sum(var) * 0.0078125f;
        float r = rsqrtf(var + 1e-5f);
#pragma unroll
        for (int i = 0; i < 4; ++i) {
            int c = lane + 32 * i;
            h[t * LDH + c] = (v[i] - mean) * r * sc[c] + bt[c];
        }
    }
}

__global__ void __launch_bounds__(TPB, 1)
vit_kernel(const float* __restrict__ x,
           const float* __restrict__ patch_w,
           const float* __restrict__ patch_b,
           const float* __restrict__ cls_token,
           const float* __restrict__ pos_embed,
           const float* __restrict__ qkv_w,
           const float* __restrict__ qkv_b,
           const float* __restrict__ out_w,
           const float* __restrict__ out_b,
           const float* __restrict__ ln1_s,
           const float* __restrict__ ln1_b,
           const float* __restrict__ ln2_s,
           const float* __restrict__ ln2_b,
           const float* __restrict__ ff1_w,
           const float* __restrict__ ff1_b,
           const float* __restrict__ ff2_w,
           const float* __restrict__ ff2_b,
           const float* __restrict__ qr1_w,
           const float* __restrict__ qr1_b,
           const float* __restrict__ qr2_w,
           const float* __restrict__ qr2_b,
           const float* __restrict__ q_weights,
           const float* __restrict__ clf_w,
           const float* __restrict__ clf_b,
           float* __restrict__ y)
{
    extern __shared__ float sm[];
    float* h   = sm + OFF_H;    // [68][128]
    float* S   = sm + OFF_S;    // [68][264]: q/ff1a 0..127 | v/ff1b 132..259
    float* kT  = sm + OFF_KT;   // [128][69]; also G = [65][132] out-proj / FF2 output
    float* G   = sm + OFF_KT;
    float* stg = sm + OFF_STG;  // weight stage [128][134] / x image / softmax probs

    const int tid  = threadIdx.x;
    const int lane = tid & 31;
    const int wid  = tid >> 5;
    const int b    = blockIdx.x;

    // ---------------- patch embed ----------------
    const float* xb = x + (size_t)b * 3072;
    for (int i = tid; i < 3072; i += TPB) stg[i] = xb[i];
    for (int i = tid; i < 6144; i += TPB) {          // patch_w [d][ck] -> S[ck][d]
        int d = i / 48, ck = i - d * 48;
        S[ck * 128 + d] = patch_w[i];
    }
    __syncthreads();
    for (int idx = tid; idx < 8192; idx += TPB) {
        int tkn = idx >> 7, d = idx & 127;
        int pi = tkn >> 3, pj = tkn & 7;
        const float* xp = stg + pi * 128 + pj * 4;
        float acc = patch_b[d];
#pragma unroll
        for (int c = 0; c < 3; ++c)
#pragma unroll
            for (int p = 0; p < 4; ++p)
#pragma unroll
                for (int q = 0; q < 4; ++q)
                    acc = fmaf(xp[c * 1024 + p * 32 + q], S[(c * 16 + p * 4 + q) * 128 + d], acc);
        h[(1 + tkn) * LDH + d] = acc + pos_embed[(1 + tkn) * 128 + d];
    }
    for (int d = tid; d < 128; d += TPB) h[d] = cls_token[d] + pos_embed[d];
    // gemm's leading __syncthreads orders these writes before stage reuse.

    const float SCALE = 0.17677669529663687f;   // 1/sqrt(32)

    for (int li = 0; li < 4; ++li) {
        const float* qw = qkv_w + li * 49152;
        const float* qb = qkv_b + li * 384;
        // Q -> S[:,0:128]
        gemm128<0, 0>(h, LDH, 0, 1, qw,          128, qb,        S,       LDS_, stg, tid, lane, wid);
        // K -> kT (transposed)
        gemm128<1, 0>(h, LDH, 0, 1, qw + 16384,  128, qb + 128,  kT,      0,    stg, tid, lane, wid);
        // V -> S[:,132:260]
        gemm128<0, 0>(h, LDH, 0, 1, qw + 32768,  128, qb + 256,  S + 132, LDS_, stg, tid, lane, wid);
        __syncthreads();   // kT / v visible to all warps

        // ---------------- attention: flat unit = (tile, head), warp-private probs ----------------
        {
            float* pw = stg + wid * 272;   // 4 rows x 68 probs
            for (int u = wid; u < 68; u += NW) {
                int hd = u & 3, tt = u >> 2;
                int ho = hd << 5;
                int t0 = tt << 2;
                float a0[4], a1[4], a64[4];
#pragma unroll
                for (int i = 0; i < 4; ++i) { a0[i] = 0.f; a1[i] = 0.f; a64[i] = 0.f; }
                const float* qrow = S + t0 * LDS_ + ho;
                const float* kb   = kT + ho * LDKT;
#pragma unroll 8
                for (int k = 0; k < 32; ++k) {
                    float k0  = kb[k * LDKT + lane];
                    float k1  = kb[k * LDKT + 32 + lane];
                    float k64 = kb[k * LDKT + 64];
#pragma unroll
                    for (int i = 0; i < 4; ++i) {
                        float qv = qrow[i * LDS_ + k];
                        a0[i]  = fmaf(qv, k0,  a0[i]);
                        a1[i]  = fmaf(qv, k1,  a1[i]);
                        a64[i] = fmaf(qv, k64, a64[i]);
                    }
                }
#pragma unroll
                for (int i = 0; i < 4; ++i) {
                    int t = t0 + i;
                    if (t >= 65) break;
                    float v0 = a0[i] * SCALE, v1 = a1[i] * SCALE, v2 = a64[i] * SCALE;
                    float m = warp_max(fmaxf(fmaxf(v0, v1), v2));
                    float e0 = __expf(v0 - m), e1 = __expf(v1 - m), e2 = __expf(v2 - m);
                    float ssum = warp_sum(e0 + e1 + (lane == 0 ? e2 : 0.f));
                    float inv = 1.f / ssum;
                    pw[i * 68 + lane]      = e0 * inv;
                    pw[i * 68 + 32 + lane] = e1 * inv;
                    if (lane == 0) pw[i * 68 + 64] = e2 * inv;
                }
                __syncwarp();
                float oc[4] = {0.f, 0.f, 0.f, 0.f};
                const float* vb = S + 132 + ho + lane;
#pragma unroll 4
                for (int uu = 0; uu < 65; ++uu) {
                    float vv = vb[uu * LDS_];
#pragma unroll
                    for (int i = 0; i < 4; ++i)
                        oc[i] = fmaf(pw[i * 68 + uu], vv, oc[i]);
                }
#pragma unroll
                for (int i = 0; i < 4; ++i)
                    if (t0 + i < 65) S[(t0 + i) * LDS_ + ho + lane] = oc[i];
                __syncwarp();
            }
        }

        // out-proj: S[:,0:128] @ W^T -> G
        gemm128<0, 0>(S, LDS_, 0, 1, out_w + li * 16384, 128, out_b + li * 128,
                      G, 132, stg, tid, lane, wid);
        __syncthreads();
        layer_norm_res(h, G, 132, ln1_s + li * 128, ln1_b + li * 128, lane, wid);

        // FF1 (relu) halves -> S[:,0:128], S[:,132:260]
        gemm128<0, 1>(h, LDH, 0, 1, ff1_w + li * 32768,         128, ff1_b + li * 256,
                      S, LDS_, stg, tid, lane, wid);
        gemm128<0, 1>(h, LDH, 0, 1, ff1_w + li * 32768 + 16384, 128, ff1_b + li * 256 + 128,
                      S + 132, LDS_, stg, tid, lane, wid);
        // FF2 (K=256, two k-stages over the S halves) -> G
        gemm128<0, 0>(S, LDS_, 132, 2, ff2_w + li * 32768, 256, ff2_b + li * 128,
                      G, 132, stg, tid, lane, wid);
        __syncthreads();
        layer_norm_res(h, G, 132, ln2_s + li * 128, ln2_b + li * 128, lane, wid);
    }
    __syncthreads();

    // ---------------- readout head (warp 0) ----------------
    if (wid == 0) {
        float accq = qr1_b[lane];
        const float* wr = qr1_w + lane * 128;
#pragma unroll 8
        for (int k = 0; k < 128; k += 4) {
            float4 hv = ld4(h + k);
            float4 wv = ld4(wr + k);
            accq = fmaf(hv.x, wv.x, accq);
            accq = fmaf(hv.y, wv.y, accq);
            accq = fmaf(hv.z, wv.z, accq);
            accq = fmaf(hv.w, wv.w, accq);
        }
        stg[lane] = fmaxf(accq, 0.f);
        __syncwarp();
        float qo[4];
#pragma unroll
        for (int m = 0; m < 4; ++m) {
            float s = qr2_b[m];
            for (int k = 0; k < 32; ++k) s = fmaf(stg[k], qr2_w[m * 32 + k], s);
            float qin = tanhf(s);
            qo[m] = cosf(qin) * cosf(q_weights[m]);
        }
        qo[1] *= qo[0]; qo[2] *= qo[1]; qo[3] *= qo[2];   // cumprod
        if (lane < 10) {
            float o = clf_b[lane];
            const float* cw = clf_w + lane * 132;
            for (int k = 0; k < 128; ++k) o = fmaf(h[k], cw[k], o);
#pragma unroll
            for (int m = 0; m < 4; ++m) o = fmaf(qo[m], cw[128 + m], o);
            y[b * 10 + lane] = o;
        }
    }
}

extern "C" void kernel_launch(void* const* d_in, const int* in_sizes, int n_in,
                              void* d_out, int out_size)
{
    const int B = in_sizes[0] / 3072;   // x = (B,3,32,32)
    cudaFuncSetAttribute(vit_kernel, cudaFuncAttributeMaxDynamicSharedMemorySize,
                         SMEM_FLOATS * (int)sizeof(float));
    vit_kernel<<<B, TPB, SMEM_FLOATS * sizeof(float)>>>(
        (const float*)d_in[0],  (const float*)d_in[1],  (const float*)d_in[2],
        (const float*)d_in[3],  (const float*)d_in[4],  (const float*)d_in[5],
        (const float*)d_in[6],  (const float*)d_in[7],  (const float*)d_in[8],
        (const float*)d_in[9],  (const float*)d_in[10], (const float*)d_in[11],
        (const float*)d_in[12], (const float*)d_in[13], (const float*)d_in[14],
        (const float*)d_in[15], (const float*)d_in[16], (const float*)d_in[17],
        (const float*)d_in[18], (const float*)d_in[19], (const float*)d_in[20],
        (const float*)d_in[21], (const float*)d_in[22], (const float*)d_in[23],
        (float*)d_out);
}

// round 7
// speedup vs baseline: 1.1071x; 1.0031x over previous
#include <cuda_runtime.h>
#include <math.h>

#define TPB 512
#define NW  16
typedef unsigned long long u64;

// shared layout (floats)
#define LDH   128            // h row stride
#define LDS_  264            // S row stride: q 0..127 | v/ff1b 132..259
#define LDKT  69             // kT row stride (conflict-free)
#define LDW   134            // weight stage row stride: lane*134 %32 = 6*lane -> conflict-free LDS.64

#define OFF_H   0
#define OFF_S   8704                      // h: 68*128
#define OFF_KT  (OFF_S + 68*LDS_)         // S: 68*264 = 17952 -> 26656   (kT / G share this area)
#define OFF_STG (OFF_KT + 128*LDKT)       // kT: 8832 -> 35488
#define SMEM_FLOATS (OFF_STG + 128*LDW)   // stage: 17152 -> 52640 floats = 210560 B

__device__ __forceinline__ float4 ld4(const float* p) {
    return *reinterpret_cast<const float4*>(p);
}
__device__ __forceinline__ u64 pack2(float x, float y) {
    u64 r; asm("mov.b64 %0, {%1, %2};" : "=l"(r) : "f"(x), "f"(y)); return r;
}
__device__ __forceinline__ void ffma2(u64& d, u64 a, u64 b) {
    asm("fma.rn.f32x2 %0, %1, %2, %0;" : "+l"(d) : "l"(a), "l"(b));
}
__device__ __forceinline__ float2 unpk(u64 v) {
    float2 r; asm("mov.b64 {%0, %1}, %2;" : "=f"(r.x), "=f"(r.y) : "l"(v)); return r;
}
__device__ __forceinline__ float warp_sum(float v) {
#pragma unroll
    for (int o = 16; o > 0; o >>= 1) v += __shfl_xor_sync(0xffffffffu, v, o);
    return v;
}
__device__ __forceinline__ float warp_max(float v) {
#pragma unroll
    for (int o = 16; o > 0; o >>= 1) v = fmaxf(v, __shfl_xor_sync(0xffffffffu, v, o));
    return v;
}

// GEMM: Out[t][j] = A[t][:] . Wg[j][:] + bias[j], t in [0,65), J = 128 per call.
// K = nkb*128; A k-chunk kb starts at A + kb*kstride. W row-major, row stride wld.
// Warp tile: 8 rows x 64 cols (rt = wid>>1 rows rt*8..+7, jh = wid&1 cols jh*64 + {lane, lane+32}).
// Row 64 handled by an all-warp gemv (warp w owns j = 8w..8w+7).
// Packed f32x2 FMA over k-pairs; acc halves summed at store time.
template<int TRANSPOSED, int RELU>
__device__ void gemm128(const float* __restrict__ A, int lda, int kstride, int nkb,
                        const float* __restrict__ Wg, int wld,
                        const float* __restrict__ bias,
                        float* __restrict__ Out, int ldo,
                        float* __restrict__ stg,
                        int tid, int lane, int wid)
{
    const int rt = wid >> 1;
    const int jb = ((wid & 1) << 6) + lane;    // cols jb, jb+32
    u64 acc[8][2];
#pragma unroll
    for (int i = 0; i < 8; ++i) { acc[i][0] = 0ull; acc[i][1] = 0ull; }
    float accg[8] = {0.f, 0.f, 0.f, 0.f, 0.f, 0.f, 0.f, 0.f};

    for (int kb = 0; kb < nkb; ++kb) {
        __syncthreads();                       // protect stage from previous users
        const float* wb = Wg + kb * 128;
        for (int idx = tid; idx < 4096; idx += TPB) {   // 128 j-rows x 32 float4
            int j  = idx & 127;
            int k4 = (idx >> 7) << 2;
            float4 v = ld4(wb + j * wld + k4);
            float* d = stg + j * LDW + k4;
            *reinterpret_cast<float2*>(d)     = make_float2(v.x, v.y);
            *reinterpret_cast<float2*>(d + 2) = make_float2(v.z, v.w);
        }
        __syncthreads();

        const float* Ab  = A + kb * kstride + rt * 8 * lda;
        const float* w0p = stg + jb * LDW;
        const float* w1p = w0p + 32 * LDW;
#pragma unroll 4
        for (int k4 = 0; k4 < 128; k4 += 4) {
            u64 w00 = *reinterpret_cast<const u64*>(w0p + k4);
            u64 w01 = *reinterpret_cast<const u64*>(w0p + k4 + 2);
            u64 w10 = *reinterpret_cast<const u64*>(w1p + k4);
            u64 w11 = *reinterpret_cast<const u64*>(w1p + k4 + 2);
#pragma unroll
            for (int i = 0; i < 8; ++i) {
                float4 a = ld4(Ab + i * lda + k4);
                u64 a01 = pack2(a.x, a.y);
                u64 a23 = pack2(a.z, a.w);
                ffma2(acc[i][0], a01, w00);
                ffma2(acc[i][0], a23, w01);
                ffma2(acc[i][1], a01, w10);
                ffma2(acc[i][1], a23, w11);
            }
        }
        // row 64 gemv partials (all warps; lane-split over k)
        const float* A64 = A + 64 * lda + kb * kstride;
        float av0 = A64[lane], av1 = A64[lane + 32], av2 = A64[lane + 64], av3 = A64[lane + 96];
#pragma unroll
        for (int jj = 0; jj < 8; ++jj) {
            const float* wc = stg + ((wid << 3) + jj) * LDW;
            accg[jj] = fmaf(av0, wc[lane],      accg[jj]);
            accg[jj] = fmaf(av1, wc[lane + 32], accg[jj]);
            accg[jj] = fmaf(av2, wc[lane + 64], accg[jj]);
            accg[jj] = fmaf(av3, wc[lane + 96], accg[jj]);
        }
    }

    float b0 = bias[jb], b1 = bias[jb + 32];
#pragma unroll
    for (int i = 0; i < 8; ++i) {
        int t = rt * 8 + i;
        float2 f0 = unpk(acc[i][0]);
        float2 f1 = unpk(acc[i][1]);
        float v0 = f0.x + f0.y + b0;
        float v1 = f1.x + f1.y + b1;
        if (RELU) { v0 = fmaxf(v0, 0.f); v1 = fmaxf(v1, 0.f); }
        if (TRANSPOSED) {
            Out[jb * LDKT + t]        = v0;
            Out[(jb + 32) * LDKT + t] = v1;
        } else {
            Out[t * ldo + jb]      = v0;
            Out[t * ldo + jb + 32] = v1;
        }
    }
#pragma unroll
    for (int jj = 0; jj < 8; ++jj) {
        float s = warp_sum(accg[jj]);
        if (lane == jj) {
            int j = (wid << 3) + jj;
            float v = s + bias[j];
            if (RELU) v = fmaxf(v, 0.f);
            if (TRANSPOSED) Out[j * LDKT + 64] = v;
            else            Out[64 * ldo + j]  = v;
        }
    }
}

// h[t] = LN(h[t] + g[t]) * sc + bt  for t < 65; g has row stride ldg
__device__ __forceinline__ void layer_norm_res(float* __restrict__ h,
                                               const float* __restrict__ g, int ldg,
                                               const float* __restrict__ sc,
                                               const float* __restrict__ bt,
                                               int lane, int wid)
{
    for (int t = wid; t < 65; t += NW) {
        float v[4];
        float s = 0.f;
#pragma unroll
        for (int i = 0; i < 4; ++i) {
            int c = lane + 32 * i;
            v[i] = h[t * LDH + c] + g[t * ldg + c];
            s += v[i];
        }
        s = warp_sum(s);
        float mean = s * 0.0078125f;
        float var = 0.f;
#pragma unroll
        for (int i = 0; i < 4; ++i) { float d = v[i] - mean; var = fmaf(d, d, var); }
        var = warp_sum(var) * 0.0078125f;
        float r = rsqrtf(var + 1e-5f);
#pragma unroll
        for (int i = 0; i < 4; ++i) {
            int c = lane + 32 * i;
            h[t * LDH + c] = (v[i] - mean) * r * sc[c] + bt[c];
        }
    }
}

__global__ void __launch_bounds__(TPB, 1)
vit_kernel(const float* __restrict__ x,
           const float* __restrict__ patch_w,
           const float* __restrict__ patch_b,
           const float* __restrict__ cls_token,
           const float* __restrict__ pos_embed,
           const float* __restrict__ qkv_w,
           const float* __restrict__ qkv_b,
           const float* __restrict__ out_w,
           const float* __restrict__ out_b,
           const float* __restrict__ ln1_s,
           const float* __restrict__ ln1_b,
           const float* __restrict__ ln2_s,
           const float* __restrict__ ln2_b,
           const float* __restrict__ ff1_w,
           const float* __restrict__ ff1_b,
           const float* __restrict__ ff2_w,
           const float* __restrict__ ff2_b,
           const float* __restrict__ qr1_w,
           const float* __restrict__ qr1_b,
           const float* __restrict__ qr2_w,
           const float* __restrict__ qr2_b,
           const float* __restrict__ q_weights,
           const float* __restrict__ clf_w,
           const float* __restrict__ clf_b,
           float* __restrict__ y)
{
    extern __shared__ float sm[];
    float* h   = sm + OFF_H;    // [68][128]
    float* S   = sm + OFF_S;    // [68][264]: q/ff1a 0..127 | v/ff1b 132..259
    float* kT  = sm + OFF_KT;   // [128][69]; also G = [65][132] out-proj / FF2 output
    float* G   = sm + OFF_KT;
    float* stg = sm + OFF_STG;  // weight stage [128][134] / x image / softmax probs

    const int tid  = threadIdx.x;
    const int lane = tid & 31;
    const int wid  = tid >> 5;
    const int b    = blockIdx.x;

    // ---------------- patch embed ----------------
    const float* xb = x + (size_t)b * 3072;
    for (int i = tid; i < 3072; i += TPB) stg[i] = xb[i];
    for (int i = tid; i < 6144; i += TPB) {          // patch_w [d][ck] -> S[ck][d]
        int d = i / 48, ck = i - d * 48;
        S[ck * 128 + d] = patch_w[i];
    }
    __syncthreads();
    for (int idx = tid; idx < 8192; idx += TPB) {
        int tkn = idx >> 7, d = idx & 127;
        int pi = tkn >> 3, pj = tkn & 7;
        const float* xp = stg + pi * 128 + pj * 4;
        float acc = patch_b[d];
#pragma unroll
        for (int c = 0; c < 3; ++c)
#pragma unroll
            for (int p = 0; p < 4; ++p)
#pragma unroll
                for (int q = 0; q < 4; ++q)
                    acc = fmaf(xp[c * 1024 + p * 32 + q], S[(c * 16 + p * 4 + q) * 128 + d], acc);
        h[(1 + tkn) * LDH + d] = acc + pos_embed[(1 + tkn) * 128 + d];
    }
    for (int d = tid; d < 128; d += TPB) h[d] = cls_token[d] + pos_embed[d];
    // gemm's leading __syncthreads orders these writes before stage reuse.

    const float SCALE = 0.17677669529663687f;   // 1/sqrt(32)

    for (int li = 0; li < 4; ++li) {
        const float* qw = qkv_w + li * 49152;
        const float* qb = qkv_b + li * 384;
        // Q -> S[:,0:128]
        gemm128<0, 0>(h, LDH, 0, 1, qw,          128, qb,        S,       LDS_, stg, tid, lane, wid);
        // K -> kT (transposed)
        gemm128<1, 0>(h, LDH, 0, 1, qw + 16384,  128, qb + 128,  kT,      0,    stg, tid, lane, wid);
        // V -> S[:,132:260]
        gemm128<0, 0>(h, LDH, 0, 1, qw + 32768,  128, qb + 256,  S + 132, LDS_, stg, tid, lane, wid);
        __syncthreads();   // kT / v visible to all warps

        // ---------------- attention: flat unit = (tile, head), warp-private probs ----------------
        {
            float* pw = stg + wid * 272;   // 4 rows x 68 probs
            for (int u = wid; u < 68; u += NW) {
                int hd = u & 3, tt = u >> 2;
                int ho = hd << 5;
                int t0 = tt << 2;
                float a0[4], a1[4], a64[4];
#pragma unroll
                for (int i = 0; i < 4; ++i) { a0[i] = 0.f; a1[i] = 0.f; a64[i] = 0.f; }
                const float* qrow = S + t0 * LDS_ + ho;
                const float* kb   = kT + ho * LDKT;
#pragma unroll 8
                for (int k = 0; k < 32; ++k) {
                    float k0  = kb[k * LDKT + lane];
                    float k1  = kb[k * LDKT + 32 + lane];
                    float k64 = kb[k * LDKT + 64];
#pragma unroll
                    for (int i = 0; i < 4; ++i) {
                        float qv = qrow[i * LDS_ + k];
                        a0[i]  = fmaf(qv, k0,  a0[i]);
                        a1[i]  = fmaf(qv, k1,  a1[i]);
                        a64[i] = fmaf(qv, k64, a64[i]);
                    }
                }
#pragma unroll
                for (int i = 0; i < 4; ++i) {
                    int t = t0 + i;
                    if (t >= 65) break;
                    float v0 = a0[i] * SCALE, v1 = a1[i] * SCALE, v2 = a64[i] * SCALE;
                    float m = warp_max(fmaxf(fmaxf(v0, v1), v2));
                    float e0 = __expf(v0 - m), e1 = __expf(v1 - m), e2 = __expf(v2 - m);
                    float ssum = warp_sum(e0 + e1 + (lane == 0 ? e2 : 0.f));
                    float inv = 1.f / ssum;
                    pw[i * 68 + lane]      = e0 * inv;
                    pw[i * 68 + 32 + lane] = e1 * inv;
                    if (lane == 0) pw[i * 68 + 64] = e2 * inv;
                }
                __syncwarp();
                float oc[4] = {0.f, 0.f, 0.f, 0.f};
                const float* vb = S + 132 + ho + lane;
#pragma unroll 4
                for (int uu = 0; uu < 65; ++uu) {
                    float vv = vb[uu * LDS_];
#pragma unroll
                    for (int i = 0; i < 4; ++i)
                        oc[i] = fmaf(pw[i * 68 + uu], vv, oc[i]);
                }
#pragma unroll
                for (int i = 0; i < 4; ++i)
                    if (t0 + i < 65) S[(t0 + i) * LDS_ + ho + lane] = oc[i];
                __syncwarp();
            }
        }

        // out-proj: S[:,0:128] @ W^T -> G
        gemm128<0, 0>(S, LDS_, 0, 1, out_w + li * 16384, 128, out_b + li * 128,
                      G, 132, stg, tid, lane, wid);
        __syncthreads();
        layer_norm_res(h, G, 132, ln1_s + li * 128, ln1_b + li * 128, lane, wid);

        // FF1 (relu) halves -> S[:,0:128], S[:,132:260]
        gemm128<0, 1>(h, LDH, 0, 1, ff1_w + li * 32768,         128, ff1_b + li * 256,
                      S, LDS_, stg, tid, lane, wid);
        gemm128<0, 1>(h, LDH, 0, 1, ff1_w + li * 32768 + 16384, 128, ff1_b + li * 256 + 128,
                      S + 132, LDS_, stg, tid, lane, wid);
        // FF2 (K=256, two k-stages over the S halves) -> G
        gemm128<0, 0>(S, LDS_, 132, 2, ff2_w + li * 32768, 256, ff2_b + li * 128,
                      G, 132, stg, tid, lane, wid);
        __syncthreads();
        layer_norm_res(h, G, 132, ln2_s + li * 128, ln2_b + li * 128, lane, wid);
    }
    __syncthreads();

    // ---------------- readout head (warp 0) ----------------
    if (wid == 0) {
        float accq = qr1_b[lane];
        const float* wr = qr1_w + lane * 128;
#pragma unroll 8
        for (int k = 0; k < 128; k += 4) {
            float4 hv = ld4(h + k);
            float4 wv = ld4(wr + k);
            accq = fmaf(hv.x, wv.x, accq);
            accq = fmaf(hv.y, wv.y, accq);
            accq = fmaf(hv.z, wv.z, accq);
            accq = fmaf(hv.w, wv.w, accq);
        }
        stg[lane] = fmaxf(accq, 0.f);
        __syncwarp();
        float qo[4];
#pragma unroll
        for (int m = 0; m < 4; ++m) {
            float s = qr2_b[m];
            for (int k = 0; k < 32; ++k) s = fmaf(stg[k], qr2_w[m * 32 + k], s);
            float qin = tanhf(s);
            qo[m] = cosf(qin) * cosf(q_weights[m]);
        }
        qo[1] *= qo[0]; qo[2] *= qo[1]; qo[3] *= qo[2];   // cumprod
        if (lane < 10) {
            float o = clf_b[lane];
            const float* cw = clf_w + lane * 132;
            for (int k = 0; k < 128; ++k) o = fmaf(h[k], cw[k], o);
#pragma unroll
            for (int m = 0; m < 4; ++m) o = fmaf(qo[m], cw[128 + m], o);
            y[b * 10 + lane] = o;
        }
    }
}

extern "C" void kernel_launch(void* const* d_in, const int* in_sizes, int n_in,
                              void* d_out, int out_size)
{
    const int B = in_sizes[0] / 3072;   // x = (B,3,32,32)
    cudaFuncSetAttribute(vit_kernel, cudaFuncAttributeMaxDynamicSharedMemorySize,
                         SMEM_FLOATS * (int)sizeof(float));
    vit_kernel<<<B, TPB, SMEM_FLOATS * sizeof(float)>>>(
        (const float*)d_in[0],  (const float*)d_in[1],  (const float*)d_in[2],
        (const float*)d_in[3],  (const float*)d_in[4],  (const float*)d_in[5],
        (const float*)d_in[6],  (const float*)d_in[7],  (const float*)d_in[8],
        (const float*)d_in[9],  (const float*)d_in[10], (const float*)d_in[11],
        (const float*)d_in[12], (const float*)d_in[13], (const float*)d_in[14],
        (const float*)d_in[15], (const float*)d_in[16], (const float*)d_in[17],
        (const float*)d_in[18], (const float*)d_in[19], (const float*)d_in[20],
        (const float*)d_in[21], (const float*)d_in[22], (const float*)d_in[23],
        (float*)d_out);
}

// round 14
// speedup vs baseline: 1.8258x; 1.6491x over previous
#include <cuda_runtime.h>
#include <cuda_bf16.h>
#include <math.h>
#include <stdint.h>

typedef unsigned int u32;

#define TPB 512

// ---- smem layout (floats) ----
#define LDH   128
#define LDS_  266            // S row stride (q/ff1a 0..127 | v/ff1b 134..261)
#define LDKT  66
#define LDG_  134

#define OFF_H   0            // h [65][128] = 8320 f
#define OFF_S   8320         // S [65][266] = 17290 f
#define OFF_A   25612        // A-stage: Ah,Al 2x(65 rows x 272B) = 8840 f ; aliased: kT [128][66]
#define A_TERM_B 17680       // bytes per A term (65*272)
#define OFF_B   34452        // B-stage: Bh,Bl 2x(128 rows x 272B) = 17408 f ; aliased: G, probs, x
#define B_TERM_B 34816       // bytes per B term (128*272)
#define SMEM_FLOATS 51860    // 207,440 B

// pre-split weights, padded-row layout identical to smem stage image:
// [layer][tile][hi/lo][n=128][136 bf16 (272B row, 128 data + pad)]
// tiles: 0=Wq 1=Wv 2=Wk 3=Wout 4=ff1a 5=ff1b 6=ff2c0 7=ff2c1
__device__ __align__(16) __nv_bfloat16 g_wsplit[4][8][2][128 * 136];

__global__ void prep_kernel(const float* __restrict__ qkv_w,
                            const float* __restrict__ out_w,
                            const float* __restrict__ ff1_w,
                            const float* __restrict__ ff2_w)
{
    int e = blockIdx.x * blockDim.x + threadIdx.x;     // 524288 total
    int layer = e >> 17;
    int r     = e & 131071;
    int tile  = r >> 14;
    int r2    = r & 16383;
    int n = r2 >> 7, k = r2 & 127;
    float w;
    if (tile == 0)      w = qkv_w[layer * 49152 + n * 128 + k];                    // Wq
    else if (tile == 1) w = qkv_w[layer * 49152 + (256 + n) * 128 + k];            // Wv
    else if (tile == 2) w = qkv_w[layer * 49152 + (128 + n) * 128 + k];            // Wk
    else if (tile == 3) w = out_w[layer * 16384 + n * 128 + k];
    else if (tile < 6)  w = ff1_w[layer * 32768 + ((tile - 4) * 128 + n) * 128 + k];
    else                w = ff2_w[layer * 32768 + n * 256 + (tile - 6) * 128 + k];
    __nv_bfloat16 hi = __float2bfloat16_rn(w);
    __nv_bfloat16 lo = __float2bfloat16_rn(w - __bfloat162float(hi));
    g_wsplit[layer][tile][0][n * 136 + k] = hi;
    g_wsplit[layer][tile][1][n * 136 + k] = lo;
}

// ---- helpers ----
__device__ __forceinline__ u32 smem_u32(const void* p) {
    u32 a;
    asm("{ .reg .u64 t; cvta.to.shared.u64 t, %1; cvt.u32.u64 %0, t; }" : "=r"(a) : "l"(p));
    return a;
}
__device__ __forceinline__ float4 ld4(const float* p) { return *reinterpret_cast<const float4*>(p); }
__device__ __forceinline__ float warp_sum(float v) {
#pragma unroll
    for (int o = 16; o > 0; o >>= 1) v += __shfl_xor_sync(0xffffffffu, v, o);
    return v;
}
__device__ __forceinline__ float warp_max(float v) {
#pragma unroll
    for (int o = 16; o > 0; o >>= 1) v = fmaxf(v, __shfl_xor_sync(0xffffffffu, v, o));
    return v;
}
__device__ __forceinline__ void ldm4(u32* r, u32 addr) {
    asm volatile("ldmatrix.sync.aligned.m8n8.x4.shared.b16 {%0,%1,%2,%3}, [%4];"
                 : "=r"(r[0]), "=r"(r[1]), "=r"(r[2]), "=r"(r[3]) : "r"(addr));
}
__device__ __forceinline__ void mma16816(float* d, const u32* a, u32 b0, u32 b1) {
    asm volatile("mma.sync.aligned.m16n8k16.row.col.f32.bf16.bf16.f32 "
                 "{%0,%1,%2,%3}, {%4,%5,%6,%7}, {%8,%9}, {%0,%1,%2,%3};"
                 : "+f"(d[0]), "+f"(d[1]), "+f"(d[2]), "+f"(d[3])
                 : "r"(a[0]), "r"(a[1]), "r"(a[2]), "r"(a[3]), "r"(b0), "r"(b1));
}

// stage Bh+Bl (contiguous 69632 B = 4352 uint4) from pre-split global into B region
__device__ __forceinline__ void stage_B(const __nv_bfloat16* __restrict__ src,
                                        float* __restrict__ Breg, int tid)
{
    const uint4* s = reinterpret_cast<const uint4*>(src);
    uint4*       d = reinterpret_cast<uint4*>(Breg);
    for (int i = tid; i < 4352; i += TPB) d[i] = s[i];
}

// convert A (65 x 128 fp32, row stride lda) -> Ah + Al bf16 padded tiles
__device__ __forceinline__ void convert_A(const float* __restrict__ src, int lda,
                                          char* __restrict__ Ast, int tid)
{
    for (int idx = tid; idx < 4160; idx += TPB) {     // 65 rows * 64 k-pairs
        int row = idx >> 6, kp = idx & 63;
        float2 v = *reinterpret_cast<const float2*>(src + row * lda + kp * 2);
        __nv_bfloat16 h0 = __float2bfloat16_rn(v.x);
        __nv_bfloat16 h1 = __float2bfloat16_rn(v.y);
        __nv_bfloat16 l0 = __float2bfloat16_rn(v.x - __bfloat162float(h0));
        __nv_bfloat16 l1 = __float2bfloat16_rn(v.y - __bfloat162float(h1));
        char* p = Ast + row * 272 + kp * 4;
        *reinterpret_cast<u32*>(p) =
            ((u32)__bfloat16_as_ushort(h1) << 16) | (u32)__bfloat16_as_ushort(h0);
        *reinterpret_cast<u32*>(p + A_TERM_B) =
            ((u32)__bfloat16_as_ushort(l1) << 16) | (u32)__bfloat16_as_ushort(l0);
    }
}

// 3-term 65x128x128 GEMM tile: rows 0-63 via HMMA (warp m16 x n32), row 64 via gemv.
// d[4][4]: 4 n-tiles x 4 f32 accum regs. g[8]: lane-partial row-64 sums (warp owns n=8*wid..+7).
__device__ void gemm_tile(const float* __restrict__ Afp, int lda,
                          u32 aB, u32 bB, const float* __restrict__ smB,
                          float (&d)[4][4], float (&g)[8], int lane, int wid)
{
    const int mg = wid >> 2, ng = wid & 3;
    const u32 aAddr = aB + (u32)((mg * 16 + (lane & 15)) * 272 + ((lane >> 4) << 4));
    const u32 bAddr = bB + (u32)((ng * 32 + ((lane >> 4) << 3) + (lane & 7)) * 272
                                 + (((lane >> 3) & 1) << 4));
#pragma unroll
    for (int term = 0; term < 3; ++term) {
        const u32 aA = aAddr + (term == 2 ? (u32)A_TERM_B : 0u);
        const u32 bA = bAddr + (term == 1 ? (u32)B_TERM_B : 0u);
#pragma unroll
        for (int ks = 0; ks < 8; ++ks) {
            u32 a[4], p[4], q[4];
            ldm4(a, aA + ks * 32);
            ldm4(p, bA + ks * 32);
            ldm4(q, bA + 16 * 272 + ks * 32);
            mma16816(d[0], a, p[0], p[1]);
            mma16816(d[1], a, p[2], p[3]);
            mma16816(d[2], a, q[0], q[1]);
            mma16816(d[3], a, q[2], q[3]);
        }
    }
    // row 64 gemv (B = hi + lo)
    const float* A64 = Afp + 64 * lda;
    const __nv_bfloat16* BH = reinterpret_cast<const __nv_bfloat16*>(smB);
    const __nv_bfloat16* BL = reinterpret_cast<const __nv_bfloat16*>(
                                  reinterpret_cast<const char*>(smB) + B_TERM_B);
    float a0 = A64[lane], a1 = A64[lane + 32], a2 = A64[lane + 64], a3 = A64[lane + 96];
#pragma unroll
    for (int jj = 0; jj < 8; ++jj) {
        int n = wid * 8 + jj;
        const __nv_bfloat16* rh = BH + n * 136;
        const __nv_bfloat16* rl = BL + n * 136;
        float s;
        s = fmaf(a0, __bfloat162float(rh[lane])      + __bfloat162float(rl[lane]),      0.f);
        s = fmaf(a1, __bfloat162float(rh[lane + 32]) + __bfloat162float(rl[lane + 32]), s);
        s = fmaf(a2, __bfloat162float(rh[lane + 64]) + __bfloat162float(rl[lane + 64]), s);
        s = fmaf(a3, __bfloat162float(rh[lane + 96]) + __bfloat162float(rl[lane + 96]), s);
        g[jj] += s;
    }
}

__device__ __forceinline__ void zero_acc(float (&d)[4][4], float (&g)[8]) {
#pragma unroll
    for (int i = 0; i < 4; ++i)
#pragma unroll
        for (int j = 0; j < 4; ++j) d[i][j] = 0.f;
#pragma unroll
    for (int j = 0; j < 8; ++j) g[j] = 0.f;
}

template<int RELU, int TRANS>
__device__ void epilogue(float (&d)[4][4], float (&g)[8],
                         const float* __restrict__ bias,
                         float* __restrict__ Out, int ldo, int lane, int wid)
{
    const int mg = wid >> 2, ng = wid & 3;
    const int r0 = mg * 16 + (lane >> 2);
    const int c0 = ng * 32 + (lane & 3) * 2;
#pragma unroll
    for (int nt = 0; nt < 4; ++nt) {
        int c = c0 + nt * 8;
        float b0 = bias[c], b1 = bias[c + 1];
        float v0 = d[nt][0] + b0, v1 = d[nt][1] + b1;
        float v2 = d[nt][2] + b0, v3 = d[nt][3] + b1;
        if (RELU) {
            v0 = fmaxf(v0, 0.f); v1 = fmaxf(v1, 0.f);
            v2 = fmaxf(v2, 0.f); v3 = fmaxf(v3, 0.f);
        }
        if (TRANS) {
            Out[c * ldo + r0]           = v0;
            Out[(c + 1) * ldo + r0]     = v1;
            Out[c * ldo + r0 + 8]       = v2;
            Out[(c + 1) * ldo + r0 + 8] = v3;
        } else {
            Out[r0 * ldo + c]           = v0;
            Out[r0 * ldo + c + 1]       = v1;
            Out[(r0 + 8) * ldo + c]     = v2;
            Out[(r0 + 8) * ldo + c + 1] = v3;
        }
    }
#pragma unroll
    for (int jj = 0; jj < 8; ++jj) {
        float s = warp_sum(g[jj]);
        if (lane == jj) {
            int j = wid * 8 + jj;
            float v = s + bias[j];
            if (RELU) v = fmaxf(v, 0.f);
            if (TRANS) Out[j * ldo + 64] = v;
            else       Out[64 * ldo + j] = v;
        }
    }
}

__device__ __forceinline__ void layer_norm_res(float* __restrict__ h,
                                               const float* __restrict__ g, int ldg,
                                               const float* __restrict__ sc,
                                               const float* __restrict__ bt,
                                               int lane, int wid)
{
    for (int t = wid; t < 65; t += 16) {
        float v[4];
        float s = 0.f;
#pragma unroll
        for (int i = 0; i < 4; ++i) {
            int c = lane + 32 * i;
            v[i] = h[t * LDH + c] + g[t * ldg + c];
            s += v[i];
        }
        s = warp_sum(s);
        float mean = s * 0.0078125f;
        float var = 0.f;
#pragma unroll
        for (int i = 0; i < 4; ++i) { float dd = v[i] - mean; var = fmaf(dd, dd, var); }
        var = warp_sum(var) * 0.0078125f;
        float rs = rsqrtf(var + 1e-5f);
#pragma unroll
        for (int i = 0; i < 4; ++i) {
            int c = lane + 32 * i;
            h[t * LDH + c] = (v[i] - mean) * rs * sc[c] + bt[c];
        }
    }
}

__global__ void __launch_bounds__(TPB, 1)
vit_kernel(const float* __restrict__ x,
           const float* __restrict__ patch_w,
           const float* __restrict__ patch_b,
           const float* __restrict__ cls_token,
           const float* __restrict__ pos_embed,
           const float* __restrict__ qkv_b,
           const float* __restrict__ out_b,
           const float* __restrict__ ln1_s,
           const float* __restrict__ ln1_b,
           const float* __restrict__ ln2_s,
           const float* __restrict__ ln2_b,
           const float* __restrict__ ff1_b,
           const float* __restrict__ ff2_b,
           const float* __restrict__ qr1_w,
           const float* __restrict__ qr1_b,
           const float* __restrict__ qr2_w,
           const float* __restrict__ qr2_b,
           const float* __restrict__ q_weights,
           const float* __restrict__ clf_w,
           const float* __restrict__ clf_b,
           float* __restrict__ y)
{
    extern __shared__ float sm[];
    float* h    = sm + OFF_H;
    float* S    = sm + OFF_S;
    float* kT   = sm + OFF_A;     // aliases A-stage (dead during attention)
    float* G    = sm + OFF_B;     // aliases B-stage (dead at epilogue time)
    char*  Ast  = (char*)(sm + OFF_A);
    float* Bstf = sm + OFF_B;

    const int tid  = threadIdx.x;
    const int lane = tid & 31;
    const int wid  = tid >> 5;
    const int b    = blockIdx.x;

    const u32 aB = smem_u32(sm + OFF_A);
    const u32 bB = smem_u32(sm + OFF_B);

    // ---------------- patch embed (SIMT) ----------------
    const float* xb = x + (size_t)b * 3072;
    for (int i = tid; i < 3072; i += TPB) Bstf[i] = xb[i];
    for (int i = tid; i < 6144; i += TPB) {          // patch_w [d][ck] -> S[ck][d]
        int d = i / 48, ck = i - d * 48;
        S[ck * 128 + d] = patch_w[i];
    }
    __syncthreads();
    for (int idx = tid; idx < 8192; idx += TPB) {
        int tkn = idx >> 7, d = idx & 127;
        int pi = tkn >> 3, pj = tkn & 7;
        const float* xp = Bstf + pi * 128 + pj * 4;
        float acc = patch_b[d];
#pragma unroll
        for (int c = 0; c < 3; ++c)
#pragma unroll
            for (int p = 0; p < 4; ++p)
#pragma unroll
                for (int q = 0; q < 4; ++q)
                    acc = fmaf(xp[c * 1024 + p * 32 + q], S[(c * 16 + p * 4 + q) * 128 + d], acc);
        h[(1 + tkn) * LDH + d] = acc + pos_embed[(1 + tkn) * 128 + d];
    }
    for (int d = tid; d < 128; d += TPB) h[d] = cls_token[d] + pos_embed[d];
    __syncthreads();

    const float SCALE = 0.17677669529663687f;
    float d_[4][4], g_[8];

    for (int li = 0; li < 4; ++li) {
        const __nv_bfloat16 (*wt)[2][128 * 136] = g_wsplit[li];
        const float* qb = qkv_b + li * 384;

        // ---------- QKV (order: Q, V, K — K last so kT can overwrite A-stage) ----------
        convert_A(h, LDH, Ast, tid);
        stage_B(wt[0][0], Bstf, tid);
        __syncthreads();
        zero_acc(d_, g_); gemm_tile(h, LDH, aB, bB, Bstf, d_, g_, lane, wid);
        __syncthreads();
        stage_B(wt[1][0], Bstf, tid);                       // V weights
        epilogue<0, 0>(d_, g_, qb, S, LDS_, lane, wid);     // Q -> S[:,0:128]
        __syncthreads();
        zero_acc(d_, g_); gemm_tile(h, LDH, aB, bB, Bstf, d_, g_, lane, wid);
        __syncthreads();
        stage_B(wt[2][0], Bstf, tid);                       // K weights
        epilogue<0, 0>(d_, g_, qb + 256, S + 134, LDS_, lane, wid);  // V
        __syncthreads();
        zero_acc(d_, g_); gemm_tile(h, LDH, aB, bB, Bstf, d_, g_, lane, wid);
        __syncthreads();
        epilogue<0, 1>(d_, g_, qb + 128, kT, LDKT, lane, wid);       // K^T over A-stage
        __syncthreads();

        // ---------- attention (SIMT; probs in B-stage region) ----------
        {
            float* pw = Bstf + wid * 272;
            for (int u = wid; u < 68; u += 16) {
                int hd = u & 3, tt = u >> 2;
                int ho = hd << 5;
                int t0 = tt << 2;
                float a0[4], a1[4], a64[4];
                const float* qrow = S + t0 * LDS_ + ho;
                const float* kb   = kT + ho * LDKT;
#pragma unroll
                for (int i = 0; i < 4; ++i) { a0[i] = 0.f; a1[i] = 0.f; a64[i] = 0.f; }
#pragma unroll 8
                for (int k = 0; k < 32; ++k) {
                    float k0  = kb[k * LDKT + lane];
                    float k1  = kb[k * LDKT + 32 + lane];
                    float k64 = kb[k * LDKT + 64];
#pragma unroll
                    for (int i = 0; i < 4; ++i) {
                        float qv = qrow[i * LDS_ + k];
                        a0[i]  = fmaf(qv, k0,  a0[i]);
                        a1[i]  = fmaf(qv, k1,  a1[i]);
                        a64[i] = fmaf(qv, k64, a64[i]);
                    }
                }
#pragma unroll
                for (int i = 0; i < 4; ++i) {
                    int t = t0 + i;
                    if (t >= 65) break;
                    float v0 = a0[i] * SCALE, v1 = a1[i] * SCALE, v2 = a64[i] * SCALE;
                    float m = warp_max(fmaxf(fmaxf(v0, v1), v2));
                    float e0 = __expf(v0 - m), e1 = __expf(v1 - m), e2 = __expf(v2 - m);
                    float ssum = warp_sum(e0 + e1 + (lane == 0 ? e2 : 0.f));
                    float inv = 1.f / ssum;
                    pw[i * 68 + lane]      = e0 * inv;
                    pw[i * 68 + 32 + lane] = e1 * inv;
                    if (lane == 0) pw[i * 68 + 64] = e2 * inv;
                }
                __syncwarp();
                float oc[4] = {0.f, 0.f, 0.f, 0.f};
                const float* vb = S + 134 + ho + lane;
#pragma unroll 4
                for (int uu = 0; uu < 65; ++uu) {
                    float vv = vb[uu * LDS_];
#pragma unroll
                    for (int i = 0; i < 4; ++i)
                        oc[i] = fmaf(pw[i * 68 + uu], vv, oc[i]);
                }
#pragma unroll
                for (int i = 0; i < 4; ++i)
                    if (t0 + i < 65) S[(t0 + i) * LDS_ + ho + lane] = oc[i];
                __syncwarp();
            }
        }
        __syncthreads();

        // ---------- out-proj: S[:,0:128] -> G ----------
        convert_A(S, LDS_, Ast, tid);                       // overwrites kT (dead)
        stage_B(wt[3][0], Bstf, tid);                       // overwrites probs (dead)
        __syncthreads();
        zero_acc(d_, g_); gemm_tile(S, LDS_, aB, bB, Bstf, d_, g_, lane, wid);
        __syncthreads();
        epilogue<0, 0>(d_, g_, out_b + li * 128, G, LDG_, lane, wid);   // G over B-stage
        __syncthreads();
        layer_norm_res(h, G, LDG_, ln1_s + li * 128, ln1_b + li * 128, lane, wid);
        __syncthreads();

        // ---------- FF1 (relu) ----------
        const float* f1b = ff1_b + li * 256;
        convert_A(h, LDH, Ast, tid);
        stage_B(wt[4][0], Bstf, tid);
        __syncthreads();
        zero_acc(d_, g_); gemm_tile(h, LDH, aB, bB, Bstf, d_, g_, lane, wid);
        __syncthreads();
        stage_B(wt[5][0], Bstf, tid);
        epilogue<1, 0>(d_, g_, f1b, S, LDS_, lane, wid);
        __syncthreads();
        zero_acc(d_, g_); gemm_tile(h, LDH, aB, bB, Bstf, d_, g_, lane, wid);
        __syncthreads();
        epilogue<1, 0>(d_, g_, f1b + 128, S + 134, LDS_, lane, wid);
        __syncthreads();

        // ---------- FF2 (K=256: two chunks, register accumulation) ----------
        convert_A(S, LDS_, Ast, tid);
        stage_B(wt[6][0], Bstf, tid);
        __syncthreads();
        zero_acc(d_, g_); gemm_tile(S, LDS_, aB, bB, Bstf, d_, g_, lane, wid);
        __syncthreads();
        convert_A(S + 134, LDS_, Ast, tid);
        stage_B(wt[7][0], Bstf, tid);
        __syncthreads();
        gemm_tile(S + 134, LDS_, aB, bB, Bstf, d_, g_, lane, wid);
        __syncthreads();
        epilogue<0, 0>(d_, g_, ff2_b + li * 128, G, LDG_, lane, wid);
        __syncthreads();
        layer_norm_res(h, G, LDG_, ln2_s + li * 128, ln2_b + li * 128, lane, wid);
        __syncthreads();
    }

    // ---------------- readout head (warp 0) ----------------
    if (wid == 0) {
        float accq = qr1_b[lane];
        const float* wr = qr1_w + lane * 128;
#pragma unroll 8
        for (int k = 0; k < 128; k += 4) {
            float4 hv = ld4(h + k);
            float4 wv = ld4(wr + k);
            accq = fmaf(hv.x, wv.x, accq);
            accq = fmaf(hv.y, wv.y, accq);
            accq = fmaf(hv.z, wv.z, accq);
            accq = fmaf(hv.w, wv.w, accq);
        }
        Bstf[lane] = fmaxf(accq, 0.f);
        __syncwarp();
        float qo[4];
#pragma unroll
        for (int m = 0; m < 4; ++m) {
            float s = qr2_b[m];
            for (int k = 0; k < 32; ++k) s = fmaf(Bstf[k], qr2_w[m * 32 + k], s);
            float qin = tanhf(s);
            qo[m] = cosf(qin) * cosf(q_weights[m]);
        }
        qo[1] *= qo[0]; qo[2] *= qo[1]; qo[3] *= qo[2];
        if (lane < 10) {
            float o = clf_b[lane];
            const float* cw = clf_w + lane * 132;
            for (int k = 0; k < 128; ++k) o = fmaf(h[k], cw[k], o);
#pragma unroll
            for (int m = 0; m < 4; ++m) o = fmaf(qo[m], cw[128 + m], o);
            y[b * 10 + lane] = o;
        }
    }
}

extern "C" void kernel_launch(void* const* d_in, const int* in_sizes, int n_in,
                              void* d_out, int out_size)
{
    const int B = in_sizes[0] / 3072;
    prep_kernel<<<1024, 512>>>(
        (const float*)d_in[5], (const float*)d_in[7],
        (const float*)d_in[13], (const float*)d_in[15]);
    cudaFuncSetAttribute(vit_kernel, cudaFuncAttributeMaxDynamicSharedMemorySize,
                         SMEM_FLOATS * (int)sizeof(float));
    vit_kernel<<<B, TPB, SMEM_FLOATS * sizeof(float)>>>(
        (const float*)d_in[0],  (const float*)d_in[1],  (const float*)d_in[2],
        (const float*)d_in[3],  (const float*)d_in[4],
        (const float*)d_in[6],  (const float*)d_in[8],
        (const float*)d_in[9],  (const float*)d_in[10], (const float*)d_in[11],
        (const float*)d_in[12], (const float*)d_in[14], (const float*)d_in[16],
        (const float*)d_in[17], (const float*)d_in[18], (const float*)d_in[19],
        (const float*)d_in[20], (const float*)d_in[21], (const float*)d_in[22],
        (const float*)d_in[23],
        (float*)d_out);
}